// round 6
// baseline (speedup 1.0000x reference)
#include <cuda_runtime.h>
#include <cstdint>

#define BB 4
#define SS 2048
#define HH 16
#define DHD 64
#define DD 1024
#define MTOT (BB * SS)   // 8192

// pos(k) within a group of 8: (k%4)*2 + k/4  -> pairs (t, t+4) become adjacent
// inverse: at position p, original k = (p%2)*4 + p/2

// Scratch.
// g_q, g_k: [B,H,S,DH] with DH pair-permuted, tf32-rounded. Q scaled by log2e/8.
// g_v: transposed per (b,h): Vt[DH][S], tf32-rounded, DH NOT permuted.
__device__ float g_q[(size_t)BB * HH * SS * DHD];
__device__ float g_k[(size_t)BB * HH * SS * DHD];
__device__ float g_v[(size_t)BB * HH * SS * DHD];
// g_xt: tf32-rounded x with K-dim pair-permuted. g_wtT: W^T [n][k], k pair-permuted.
__device__ float g_xt[(size_t)MTOT * DD];
__device__ float g_wtT[3][(size_t)DD * DD];

__device__ __forceinline__ uint32_t f2tf(float f) {
    uint32_t u;
    asm("cvt.rna.tf32.f32 %0, %1;" : "=r"(u) : "f"(f));
    return u;
}
__device__ __forceinline__ float f2tff(float f) { return __uint_as_float(f2tf(f)); }

__device__ __forceinline__ void mma8(float& d0, float& d1, float& d2, float& d3,
                                     uint32_t a0, uint32_t a1, uint32_t a2, uint32_t a3,
                                     uint32_t b0, uint32_t b1) {
    asm volatile(
        "mma.sync.aligned.m16n8k8.row.col.f32.tf32.tf32.f32 "
        "{%0,%1,%2,%3}, {%4,%5,%6,%7}, {%8,%9}, {%0,%1,%2,%3};"
        : "+f"(d0), "+f"(d1), "+f"(d2), "+f"(d3)
        : "r"(a0), "r"(a1), "r"(a2), "r"(a3), "r"(b0), "r"(b1));
}

__device__ __forceinline__ void cp16(void* smem, const void* gmem) {
    uint32_t s = (uint32_t)__cvta_generic_to_shared(smem);
    asm volatile("cp.async.cg.shared.global [%0], [%1], 16;" :: "r"(s), "l"(gmem));
}
#define CP_COMMIT() asm volatile("cp.async.commit_group;")
#define CP_WAIT(N)  asm volatile("cp.async.wait_group %0;" :: "n"(N))

// ============================================================================
// Kernel 0a: x -> tf32-rounded, K-dim pair-permuted. Each thread: 8 floats.
// out group [k0,k4,k1,k5 | k2,k6,k3,k7]
// ============================================================================
__global__ __launch_bounds__(256) void cvt_x_kernel(const float4* __restrict__ src) {
    int j = blockIdx.x * 256 + threadIdx.x;   // group index, 8 floats each
    float4 a = src[2 * j];
    float4 b = src[2 * j + 1];
    float4 o0, o1;
    o0.x = f2tff(a.x); o0.y = f2tff(b.x); o0.z = f2tff(a.y); o0.w = f2tff(b.y);
    o1.x = f2tff(a.z); o1.y = f2tff(b.z); o1.z = f2tff(a.w); o1.w = f2tff(b.w);
    ((float4*)g_xt)[2 * j]     = o0;
    ((float4*)g_xt)[2 * j + 1] = o1;
}

// ============================================================================
// Kernel 0b: W [k][n] -> Wt [n][k] tf32-rounded, k pair-permuted.
// grid (32, 32, 3), block (32, 8). 32x32 tiles via smem.
// ============================================================================
__global__ __launch_bounds__(256) void cvt_w_kernel(
    const float* __restrict__ Wq, const float* __restrict__ Wk,
    const float* __restrict__ Wv)
{
    __shared__ float tile[32][33];
    const int mat = blockIdx.z;
    const float* W = (mat == 0) ? Wq : (mat == 1) ? Wk : Wv;
    float* Wt = g_wtT[mat];
    const int k0 = blockIdx.x * 32;
    const int n0 = blockIdx.y * 32;
    const int tx = threadIdx.x, ty = threadIdx.y;

    #pragma unroll
    for (int i = 0; i < 4; i++)
        tile[ty + i * 8][tx] = W[(size_t)(k0 + ty + i * 8) * DD + n0 + tx];
    __syncthreads();
    const int kp = (tx & 24) + ((tx & 3) * 2 + ((tx >> 2) & 1));  // permuted k within 32
    #pragma unroll
    for (int i = 0; i < 4; i++)
        Wt[(size_t)(n0 + ty + i * 8) * DD + k0 + kp] = f2tff(tile[tx][ty + i * 8]);
}

// ============================================================================
// Kernel 1: fused QKV projection GEMM (tf32 mma, cp.async 2-stage)
// 128x128 block tile, 4 warps, warp tile 64x64, k-step 32.
// A-frags and B-frags via conflict-free LDS.64 (pair-permuted k).
// Epilogue: Q (scaled by log2e/8) & K written DH-pair-permuted; V transposed.
// ============================================================================
#define GST 40                 // smem row stride (floats)
#define XS_ST (128 * GST)
#define WS_ST (128 * GST)

__global__ __launch_bounds__(128) void qkv_gemm_kernel(
    const float* __restrict__ bq, const float* __restrict__ bk,
    const float* __restrict__ bv)
{
    extern __shared__ float sm[];
    float* Xs = sm;                 // 2 x [128 rows][GST]
    float* Wsm = sm + 2 * XS_ST;    // 2 x [128 n-rows][GST]

    const int mt = blockIdx.x;
    const int nt = blockIdx.y;
    const int mat = nt >> 3;
    const int n0 = (nt & 7) * 128;

    const float* Wtb = g_wtT[mat];
    const float* bias = (mat == 0) ? bq : (mat == 1) ? bk : bv;
    float* outp = (mat == 0) ? g_q : (mat == 1) ? g_k : g_v;
    const float scale = (mat == 0) ? 0.18033688f : 1.0f;   // log2e/8 for Q

    const int tid  = threadIdx.x;
    const int warp = tid >> 5;
    const int lane = tid & 31;
    const int g    = lane >> 2;
    const int tig  = lane & 3;
    const int wm   = (warp & 1) * 64;
    const int wn   = (warp >> 1) * 64;
    const int m0   = mt * 128;

    const float* xb = g_xt + (size_t)m0 * DD;

    float acc[4][8][4];
    #pragma unroll
    for (int mi = 0; mi < 4; mi++)
        #pragma unroll
        for (int ni = 0; ni < 8; ni++)
            #pragma unroll
            for (int r = 0; r < 4; r++) acc[mi][ni][r] = 0.0f;

    auto load_stage = [&](int t, int st) {
        const int k0 = t * 32;
        float* Xst = Xs + st * XS_ST;
        float* Wst = Wsm + st * WS_ST;
        #pragma unroll
        for (int i = 0; i < 8; i++) {
            int idx = tid + i * 128;
            int r = idx >> 3, c = (idx & 7) << 2;     // X 128 rows x 32 k
            cp16(&Xst[r * GST + c], xb + (size_t)r * DD + k0 + c);
        }
        #pragma unroll
        for (int i = 0; i < 8; i++) {
            int idx = tid + i * 128;
            int r = idx >> 3, c = (idx & 7) << 2;     // Wt 128 n-rows x 32 k
            cp16(&Wst[r * GST + c], Wtb + (size_t)(n0 + r) * DD + k0 + c);
        }
        CP_COMMIT();
    };

    load_stage(0, 0);

    const int NT = DD / 32;   // 32
    for (int t = 0; t < NT; t++) {
        if (t + 1 < NT) { load_stage(t + 1, (t + 1) & 1); CP_WAIT(1); }
        else            { CP_WAIT(0); }
        __syncthreads();

        const float* Xst = Xs + (t & 1) * XS_ST;
        const float* Wst = Wsm + (t & 1) * WS_ST;
        #pragma unroll
        for (int kk = 0; kk < 4; kk++) {
            const int k8 = kk * 8;
            uint32_t A[4][4];
            #pragma unroll
            for (int mi = 0; mi < 4; mi++) {
                const int row = wm + mi * 16;
                float2 lo = *(const float2*)&Xst[(row + g) * GST + k8 + 2 * tig];
                float2 hi = *(const float2*)&Xst[(row + g + 8) * GST + k8 + 2 * tig];
                A[mi][0] = __float_as_uint(lo.x);  // k8+tig
                A[mi][1] = __float_as_uint(hi.x);
                A[mi][2] = __float_as_uint(lo.y);  // k8+tig+4
                A[mi][3] = __float_as_uint(hi.y);
            }
            #pragma unroll
            for (int ni = 0; ni < 8; ni++) {
                const int col = wn + ni * 8 + g;
                float2 bb = *(const float2*)&Wst[col * GST + k8 + 2 * tig];
                uint32_t b0 = __float_as_uint(bb.x);
                uint32_t b1 = __float_as_uint(bb.y);
                #pragma unroll
                for (int mi = 0; mi < 4; mi++)
                    mma8(acc[mi][ni][0], acc[mi][ni][1], acc[mi][ni][2], acc[mi][ni][3],
                         A[mi][0], A[mi][1], A[mi][2], A[mi][3], b0, b1);
            }
        }
        __syncthreads();
    }

    // Epilogue
    #pragma unroll
    for (int mi = 0; mi < 4; mi++) {
        #pragma unroll
        for (int ni = 0; ni < 8; ni++) {
            const int n = n0 + wn + ni * 8 + 2 * tig;   // even
            const int h = n >> 6;
            const int dh = n & 63;
            const float bv0 = bias[n];
            const float bv1 = bias[n + 1];
            const int mbase = m0 + wm + mi * 16;
            // permuted positions within the dh group of 8 (dh%8 = 2*tig)
            const int dhg = dh & ~7;
            const int p0 = 2 * ((2 * tig) & 3) + (tig >> 1);        // pos(2t): 0,4,1,5
            const int p1 = 2 * ((2 * tig + 1) & 3) + ((2 * tig + 1) >> 2); // pos(2t+1): 2,6,3,7
            #pragma unroll
            for (int half = 0; half < 2; half++) {
                const int m = mbase + g + half * 8;
                const int b = m >> 11, s = m & 2047;
                const float v0 = f2tff((acc[mi][ni][2 * half]     + bv0) * scale);
                const float v1 = f2tff((acc[mi][ni][2 * half + 1] + bv1) * scale);
                if (mat == 2) {
                    // V transposed: Vt[dh][s] per (b,h), DH unpermuted
                    float* vtb = outp + (size_t)(b * HH + h) * (DHD * SS);
                    vtb[(size_t)dh * SS + s] = v0;
                    vtb[(size_t)(dh + 1) * SS + s] = v1;
                } else {
                    float* ob = outp + ((size_t)(b * HH + h) * SS + s) * DHD + dhg;
                    ob[p0] = v0;
                    ob[p1] = v1;
                }
            }
        }
    }
}

// ============================================================================
// Kernel 2: flash attention (tf32 mma, base-2 online softmax)
// grid = (16 q-tiles of 128, 64 bh), 128 threads (4 warps x 32 q-rows).
// 64-key K/V tiles double-buffered; softmax per 32-key chunk.
// K/Q DH pair-permuted -> LDS.64 frags; V transposed -> conflict-free.
// ============================================================================
#define KST 72             // Q/K smem row stride
#define VST 68             // Vt smem row stride
#define PST 36             // P smem row stride
#define KTILE_F (64 * KST) // floats per K stage (64 keys)
#define VTILE_F (64 * VST) // floats per V stage (64 dh rows x 64 keys)
#define Q_FLOATS (128 * KST)

__global__ __launch_bounds__(128, 2) void attn_kernel(float* __restrict__ out)
{
    extern __shared__ float sm[];
    float* QP = sm;                        // Q (128 x KST), later reused as P
    float* Ks = sm + Q_FLOATS;             // 2 x 64 x KST
    float* Vs = Ks + 2 * KTILE_F;          // 2 x 64 x VST

    const int bh = blockIdx.y;
    const int q0 = blockIdx.x * 128;

    const float* qb  = g_q + (size_t)bh * SS * DHD + (size_t)q0 * DHD;
    const float* kb  = g_k + (size_t)bh * SS * DHD;
    const float* vtb = g_v + (size_t)bh * (DHD * SS);   // Vt[dh][s]

    const int tid  = threadIdx.x;
    const int warp = tid >> 5;
    const int lane = tid & 31;
    const int g    = lane >> 2;
    const int tig  = lane & 3;

    // Load Q tile 128x64 to smem
    #pragma unroll
    for (int i = 0; i < 16; i++) {
        int idx = tid + i * 128;
        int r = idx >> 4, c = (idx & 15) << 2;
        *(float4*)&QP[r * KST + c] = *(const float4*)(qb + (size_t)r * DHD + c);
    }
    __syncthreads();

    // Q A-fragments (permuted DH -> LDS.64 pairs)
    uint32_t QA[8][2][4];
    #pragma unroll
    for (int kk = 0; kk < 8; kk++) {
        #pragma unroll
        for (int mi = 0; mi < 2; mi++) {
            const int qrow = warp * 32 + mi * 16;
            float2 lo = *(const float2*)&QP[(qrow + g) * KST + kk * 8 + 2 * tig];
            float2 hi = *(const float2*)&QP[(qrow + g + 8) * KST + kk * 8 + 2 * tig];
            QA[kk][mi][0] = __float_as_uint(lo.x);
            QA[kk][mi][1] = __float_as_uint(hi.x);
            QA[kk][mi][2] = __float_as_uint(lo.y);
            QA[kk][mi][3] = __float_as_uint(hi.y);
        }
    }

    float O[2][8][4];
    #pragma unroll
    for (int mi = 0; mi < 2; mi++)
        #pragma unroll
        for (int ni = 0; ni < 8; ni++)
            #pragma unroll
            for (int r = 0; r < 4; r++) O[mi][ni][r] = 0.0f;

    float mrun[2][2], lrun[2][2];
    #pragma unroll
    for (int mi = 0; mi < 2; mi++) {
        mrun[mi][0] = -1e30f; mrun[mi][1] = -1e30f;
        lrun[mi][0] = 0.0f;   lrun[mi][1] = 0.0f;
    }

    float* Pw = QP + warp * (32 * PST);   // per-warp 32x36 P region (overlaps Q)

    auto load_kv = [&](int t, int st) {
        #pragma unroll
        for (int i = 0; i < 8; i++) {
            int idx = tid + i * 128;
            int r = idx >> 4, c = (idx & 15) << 2;     // K: 64 keys x 64 dh
            cp16(&Ks[st * KTILE_F + r * KST + c], kb + (size_t)(t * 64 + r) * DHD + c);
        }
        #pragma unroll
        for (int i = 0; i < 8; i++) {
            int idx = tid + i * 128;
            int r = idx >> 4, c = (idx & 15) << 2;     // Vt: 64 dh x 64 keys
            cp16(&Vs[st * VTILE_F + r * VST + c], vtb + (size_t)r * SS + t * 64 + c);
        }
        CP_COMMIT();
    };

    load_kv(0, 0);

    const int NT = SS / 64;   // 32 tiles
    for (int t = 0; t < NT; t++) {
        if (t + 1 < NT) { load_kv(t + 1, (t + 1) & 1); CP_WAIT(1); }
        else            { CP_WAIT(0); }
        __syncthreads();

        const float* Kst = Ks + (t & 1) * KTILE_F;
        const float* Vst = Vs + (t & 1) * VTILE_F;

        #pragma unroll
        for (int ch = 0; ch < 2; ch++) {     // two 32-key chunks
            const float* Kc = Kst + (ch * 32) * KST;
            const int vcol = ch * 32;

            // S = Q @ K^T : 32 rows x 32 keys per warp
            float S[2][4][4];
            #pragma unroll
            for (int mi = 0; mi < 2; mi++)
                #pragma unroll
                for (int ni = 0; ni < 4; ni++)
                    #pragma unroll
                    for (int r = 0; r < 4; r++) S[mi][ni][r] = 0.0f;

            #pragma unroll
            for (int kk = 0; kk < 8; kk++) {
                const int k8 = kk * 8;
                #pragma unroll
                for (int ni = 0; ni < 4; ni++) {
                    float2 bb = *(const float2*)&Kc[(ni * 8 + g) * KST + k8 + 2 * tig];
                    uint32_t b0 = __float_as_uint(bb.x);
                    uint32_t b1 = __float_as_uint(bb.y);
                    #pragma unroll
                    for (int mi = 0; mi < 2; mi++)
                        mma8(S[mi][ni][0], S[mi][ni][1], S[mi][ni][2], S[mi][ni][3],
                             QA[kk][mi][0], QA[kk][mi][1], QA[kk][mi][2], QA[kk][mi][3],
                             b0, b1);
                }
            }

            // Base-2 online softmax per mi (row pairs g, g+8)
            #pragma unroll
            for (int mi = 0; mi < 2; mi++) {
                float mt0 = -1e30f, mt1 = -1e30f;
                #pragma unroll
                for (int ni = 0; ni < 4; ni++) {
                    mt0 = fmaxf(mt0, fmaxf(S[mi][ni][0], S[mi][ni][1]));
                    mt1 = fmaxf(mt1, fmaxf(S[mi][ni][2], S[mi][ni][3]));
                }
                mt0 = fmaxf(mt0, __shfl_xor_sync(0xffffffffu, mt0, 1));
                mt0 = fmaxf(mt0, __shfl_xor_sync(0xffffffffu, mt0, 2));
                mt1 = fmaxf(mt1, __shfl_xor_sync(0xffffffffu, mt1, 1));
                mt1 = fmaxf(mt1, __shfl_xor_sync(0xffffffffu, mt1, 2));

                const float mn0 = fmaxf(mrun[mi][0], mt0);
                const float mn1 = fmaxf(mrun[mi][1], mt1);
                const float al0 = exp2f(mrun[mi][0] - mn0);
                const float al1 = exp2f(mrun[mi][1] - mn1);

                float rs0 = 0.0f, rs1 = 0.0f;
                #pragma unroll
                for (int ni = 0; ni < 4; ni++) {
                    S[mi][ni][0] = exp2f(S[mi][ni][0] - mn0);
                    S[mi][ni][1] = exp2f(S[mi][ni][1] - mn0);
                    S[mi][ni][2] = exp2f(S[mi][ni][2] - mn1);
                    S[mi][ni][3] = exp2f(S[mi][ni][3] - mn1);
                    rs0 += S[mi][ni][0] + S[mi][ni][1];
                    rs1 += S[mi][ni][2] + S[mi][ni][3];
                }
                rs0 += __shfl_xor_sync(0xffffffffu, rs0, 1);
                rs0 += __shfl_xor_sync(0xffffffffu, rs0, 2);
                rs1 += __shfl_xor_sync(0xffffffffu, rs1, 1);
                rs1 += __shfl_xor_sync(0xffffffffu, rs1, 2);

                lrun[mi][0] = lrun[mi][0] * al0 + rs0;
                lrun[mi][1] = lrun[mi][1] * al1 + rs1;
                mrun[mi][0] = mn0;
                mrun[mi][1] = mn1;

                if (!__all_sync(0xffffffffu, (al0 == 1.0f) & (al1 == 1.0f))) {
                    #pragma unroll
                    for (int ni = 0; ni < 8; ni++) {
                        O[mi][ni][0] *= al0; O[mi][ni][1] *= al0;
                        O[mi][ni][2] *= al1; O[mi][ni][3] *= al1;
                    }
                }
            }

            // Stage P (tf32-rounded) to per-warp smem for C->A relayout
            #pragma unroll
            for (int mi = 0; mi < 2; mi++) {
                #pragma unroll
                for (int ni = 0; ni < 4; ni++) {
                    const int base = (mi * 16 + g) * PST + ni * 8 + 2 * tig;
                    float2 p0, p1;
                    p0.x = f2tff(S[mi][ni][0]); p0.y = f2tff(S[mi][ni][1]);
                    p1.x = f2tff(S[mi][ni][2]); p1.y = f2tff(S[mi][ni][3]);
                    *(float2*)&Pw[base] = p0;
                    *(float2*)&Pw[base + 8 * PST] = p1;
                }
            }
            __syncwarp();

            // O += P @ V   (V B-frags from transposed Vt rows: conflict-free)
            #pragma unroll
            for (int kk = 0; kk < 4; kk++) {
                const int k8 = kk * 8;
                uint32_t pa[2][4];
                #pragma unroll
                for (int mi = 0; mi < 2; mi++) {
                    const int base = (mi * 16 + g) * PST;
                    pa[mi][0] = __float_as_uint(Pw[base + k8 + tig]);
                    pa[mi][1] = __float_as_uint(Pw[base + 8 * PST + k8 + tig]);
                    pa[mi][2] = __float_as_uint(Pw[base + k8 + tig + 4]);
                    pa[mi][3] = __float_as_uint(Pw[base + 8 * PST + k8 + tig + 4]);
                }
                #pragma unroll
                for (int ni = 0; ni < 8; ni++) {
                    const float* vrow = &Vst[(ni * 8 + g) * VST + vcol + k8];
                    uint32_t b0 = __float_as_uint(vrow[tig]);
                    uint32_t b1 = __float_as_uint(vrow[tig + 4]);
                    #pragma unroll
                    for (int mi = 0; mi < 2; mi++)
                        mma8(O[mi][ni][0], O[mi][ni][1], O[mi][ni][2], O[mi][ni][3],
                             pa[mi][0], pa[mi][1], pa[mi][2], pa[mi][3], b0, b1);
                }
            }
            __syncwarp();
        }
        __syncthreads();   // all warps done with this K/V stage before reload
    }

    // Normalize + write [B,S,H*DH]
    const int b = bh >> 4;
    const int h = bh & 15;
    #pragma unroll
    for (int mi = 0; mi < 2; mi++) {
        const float il0 = 1.0f / lrun[mi][0];
        const float il1 = 1.0f / lrun[mi][1];
        #pragma unroll
        for (int ni = 0; ni < 8; ni++) {
            const int dh = ni * 8 + 2 * tig;
            {
                int s = q0 + warp * 32 + mi * 16 + g;
                float2 v; v.x = O[mi][ni][0] * il0; v.y = O[mi][ni][1] * il0;
                *(float2*)(out + ((size_t)(b * SS + s) * HH + h) * DHD + dh) = v;
            }
            {
                int s = q0 + warp * 32 + mi * 16 + g + 8;
                float2 v; v.x = O[mi][ni][2] * il1; v.y = O[mi][ni][3] * il1;
                *(float2*)(out + ((size_t)(b * SS + s) * HH + h) * DHD + dh) = v;
            }
        }
    }
}

// ============================================================================
// Launch
// ============================================================================
extern "C" void kernel_launch(void* const* d_in, const int* in_sizes, int n_in,
                              void* d_out, int out_size)
{
    const float* x  = (const float*)d_in[0];
    const float* Wq = (const float*)d_in[1];
    const float* bq = (const float*)d_in[2];
    const float* Wk = (const float*)d_in[3];
    const float* bk = (const float*)d_in[4];
    const float* Wv = (const float*)d_in[5];
    const float* bv = (const float*)d_in[6];
    float* out = (float*)d_out;

    // Prep: permute+round x; transpose+permute+round W
    {
        int ngx = MTOT * DD / 8;    // 8 floats per thread
        cvt_x_kernel<<<ngx / 256, 256>>>((const float4*)x);
        dim3 gw(32, 32, 3);
        cvt_w_kernel<<<gw, dim3(32, 8)>>>(Wq, Wk, Wv);
    }

    // QKV GEMM
    {
        const int smem = (2 * XS_ST + 2 * WS_ST) * (int)sizeof(float);   // 81920
        cudaFuncSetAttribute(qkv_gemm_kernel,
                             cudaFuncAttributeMaxDynamicSharedMemorySize, smem);
        dim3 grd(MTOT / 128, 24);
        qkv_gemm_kernel<<<grd, 128, smem>>>(bq, bk, bv);
    }

    // Attention
    {
        const int smem = (Q_FLOATS + 2 * KTILE_F + 2 * VTILE_F) * (int)sizeof(float); // 108544
        cudaFuncSetAttribute(attn_kernel,
                             cudaFuncAttributeMaxDynamicSharedMemorySize, smem);
        dim3 grd(SS / 128, BB * HH);
        attn_kernel<<<grd, 128, smem>>>(out);
    }
}

// round 9
// speedup vs baseline: 1.0922x; 1.0922x over previous
#include <cuda_runtime.h>
#include <cstdint>

#define BB 4
#define SS 2048
#define HH 16
#define DHD 64
#define DD 1024
#define MTOT (BB * SS)   // 8192

// pos(k) within a group of 8: (k%4)*2 + k/4  -> pairs (t, t+4) become adjacent
// Scratch.
// g_q, g_k: [B,H,S,DH], DH pair-permuted, tf32-rounded. Q scaled by log2e/8.
// g_v: [B,H,S,DH] natural layout, tf32-rounded.
__device__ float g_q[(size_t)BB * HH * SS * DHD];
__device__ float g_k[(size_t)BB * HH * SS * DHD];
__device__ float g_v[(size_t)BB * HH * SS * DHD];
// g_xt: tf32-rounded x, K-dim pair-permuted. g_wtT: W^T [n][k], k pair-permuted.
__device__ float g_xt[(size_t)MTOT * DD];
__device__ float g_wtT[3][(size_t)DD * DD];

__device__ __forceinline__ uint32_t f2tf(float f) {
    uint32_t u;
    asm("cvt.rna.tf32.f32 %0, %1;" : "=r"(u) : "f"(f));
    return u;
}
__device__ __forceinline__ float f2tff(float f) { return __uint_as_float(f2tf(f)); }

__device__ __forceinline__ void mma8(float& d0, float& d1, float& d2, float& d3,
                                     uint32_t a0, uint32_t a1, uint32_t a2, uint32_t a3,
                                     uint32_t b0, uint32_t b1) {
    asm volatile(
        "mma.sync.aligned.m16n8k8.row.col.f32.tf32.tf32.f32 "
        "{%0,%1,%2,%3}, {%4,%5,%6,%7}, {%8,%9}, {%0,%1,%2,%3};"
        : "+f"(d0), "+f"(d1), "+f"(d2), "+f"(d3)
        : "r"(a0), "r"(a1), "r"(a2), "r"(a3), "r"(b0), "r"(b1));
}

__device__ __forceinline__ void cp16(void* smem, const void* gmem) {
    uint32_t s = (uint32_t)__cvta_generic_to_shared(smem);
    asm volatile("cp.async.cg.shared.global [%0], [%1], 16;" :: "r"(s), "l"(gmem));
}
#define CP_COMMIT() asm volatile("cp.async.commit_group;")
#define CP_WAIT(N)  asm volatile("cp.async.wait_group %0;" :: "n"(N))

// ============================================================================
// Kernel 0a: x -> tf32-rounded, K-dim pair-permuted.
// ============================================================================
__global__ __launch_bounds__(256) void cvt_x_kernel(const float4* __restrict__ src) {
    int j = blockIdx.x * 256 + threadIdx.x;
    float4 a = src[2 * j];
    float4 b = src[2 * j + 1];
    float4 o0, o1;
    o0.x = f2tff(a.x); o0.y = f2tff(b.x); o0.z = f2tff(a.y); o0.w = f2tff(b.y);
    o1.x = f2tff(a.z); o1.y = f2tff(b.z); o1.z = f2tff(a.w); o1.w = f2tff(b.w);
    ((float4*)g_xt)[2 * j]     = o0;
    ((float4*)g_xt)[2 * j + 1] = o1;
}

// ============================================================================
// Kernel 0b: W [k][n] -> Wt [n][k] tf32-rounded, k pair-permuted.
// ============================================================================
__global__ __launch_bounds__(256) void cvt_w_kernel(
    const float* __restrict__ Wq, const float* __restrict__ Wk,
    const float* __restrict__ Wv)
{
    __shared__ float tile[32][33];
    const int mat = blockIdx.z;
    const float* W = (mat == 0) ? Wq : (mat == 1) ? Wk : Wv;
    float* Wt = g_wtT[mat];
    const int k0 = blockIdx.x * 32;
    const int n0 = blockIdx.y * 32;
    const int tx = threadIdx.x, ty = threadIdx.y;

    #pragma unroll
    for (int i = 0; i < 4; i++)
        tile[ty + i * 8][tx] = W[(size_t)(k0 + ty + i * 8) * DD + n0 + tx];
    __syncthreads();
    const int kp = (tx & 24) + ((tx & 3) * 2 + ((tx >> 2) & 1));
    #pragma unroll
    for (int i = 0; i < 4; i++)
        Wt[(size_t)(n0 + ty + i * 8) * DD + k0 + kp] = f2tff(tile[tx][ty + i * 8]);
}

// ============================================================================
// Kernel 1: fused QKV projection GEMM (tf32 mma, cp.async 2-stage)
// Epilogue: Q (scaled, DH-permuted), K (DH-permuted), V (natural, coalesced).
// ============================================================================
#define GST 40
#define XS_ST (128 * GST)
#define WS_ST (128 * GST)

__global__ __launch_bounds__(128, 2) void qkv_gemm_kernel(
    const float* __restrict__ bq, const float* __restrict__ bk,
    const float* __restrict__ bv)
{
    extern __shared__ float sm[];
    float* Xs = sm;
    float* Wsm = sm + 2 * XS_ST;

    const int mt = blockIdx.x;
    const int nt = blockIdx.y;
    const int mat = nt >> 3;
    const int n0 = (nt & 7) * 128;

    const float* Wtb = g_wtT[mat];
    const float* bias = (mat == 0) ? bq : (mat == 1) ? bk : bv;
    float* outp = (mat == 0) ? g_q : (mat == 1) ? g_k : g_v;
    const float scale = (mat == 0) ? 0.18033688f : 1.0f;   // log2e/8 for Q

    const int tid  = threadIdx.x;
    const int warp = tid >> 5;
    const int lane = tid & 31;
    const int g    = lane >> 2;
    const int tig  = lane & 3;
    const int wm   = (warp & 1) * 64;
    const int wn   = (warp >> 1) * 64;
    const int m0   = mt * 128;

    const float* xb = g_xt + (size_t)m0 * DD;

    float acc[4][8][4];
    #pragma unroll
    for (int mi = 0; mi < 4; mi++)
        #pragma unroll
        for (int ni = 0; ni < 8; ni++)
            #pragma unroll
            for (int r = 0; r < 4; r++) acc[mi][ni][r] = 0.0f;

    auto load_stage = [&](int t, int st) {
        const int k0 = t * 32;
        float* Xst = Xs + st * XS_ST;
        float* Wst = Wsm + st * WS_ST;
        #pragma unroll
        for (int i = 0; i < 8; i++) {
            int idx = tid + i * 128;
            int r = idx >> 3, c = (idx & 7) << 2;
            cp16(&Xst[r * GST + c], xb + (size_t)r * DD + k0 + c);
        }
        #pragma unroll
        for (int i = 0; i < 8; i++) {
            int idx = tid + i * 128;
            int r = idx >> 3, c = (idx & 7) << 2;
            cp16(&Wst[r * GST + c], Wtb + (size_t)(n0 + r) * DD + k0 + c);
        }
        CP_COMMIT();
    };

    load_stage(0, 0);

    const int NT = DD / 32;
    for (int t = 0; t < NT; t++) {
        if (t + 1 < NT) { load_stage(t + 1, (t + 1) & 1); CP_WAIT(1); }
        else            { CP_WAIT(0); }
        __syncthreads();

        const float* Xst = Xs + (t & 1) * XS_ST;
        const float* Wst = Wsm + (t & 1) * WS_ST;
        #pragma unroll
        for (int kk = 0; kk < 4; kk++) {
            const int k8 = kk * 8;
            uint32_t A[4][4];
            #pragma unroll
            for (int mi = 0; mi < 4; mi++) {
                const int row = wm + mi * 16;
                float2 lo = *(const float2*)&Xst[(row + g) * GST + k8 + 2 * tig];
                float2 hi = *(const float2*)&Xst[(row + g + 8) * GST + k8 + 2 * tig];
                A[mi][0] = __float_as_uint(lo.x);
                A[mi][1] = __float_as_uint(hi.x);
                A[mi][2] = __float_as_uint(lo.y);
                A[mi][3] = __float_as_uint(hi.y);
            }
            #pragma unroll
            for (int ni = 0; ni < 8; ni++) {
                const int col = wn + ni * 8 + g;
                float2 bb = *(const float2*)&Wst[col * GST + k8 + 2 * tig];
                uint32_t b0 = __float_as_uint(bb.x);
                uint32_t b1 = __float_as_uint(bb.y);
                #pragma unroll
                for (int mi = 0; mi < 4; mi++)
                    mma8(acc[mi][ni][0], acc[mi][ni][1], acc[mi][ni][2], acc[mi][ni][3],
                         A[mi][0], A[mi][1], A[mi][2], A[mi][3], b0, b1);
            }
        }
        __syncthreads();
    }

    // Epilogue
    #pragma unroll
    for (int mi = 0; mi < 4; mi++) {
        #pragma unroll
        for (int ni = 0; ni < 8; ni++) {
            const int n = n0 + wn + ni * 8 + 2 * tig;   // even
            const int h = n >> 6;
            const int dh = n & 63;
            const float bv0 = bias[n];
            const float bv1 = bias[n + 1];
            const int mbase = m0 + wm + mi * 16;
            const int dhg = dh & ~7;
            const int p0 = 2 * ((2 * tig) & 3) + (tig >> 1);
            const int p1 = 2 * ((2 * tig + 1) & 3) + ((2 * tig + 1) >> 2);
            #pragma unroll
            for (int half = 0; half < 2; half++) {
                const int m = mbase + g + half * 8;
                const int b = m >> 11, s = m & 2047;
                const float v0 = f2tff((acc[mi][ni][2 * half]     + bv0) * scale);
                const float v1 = f2tff((acc[mi][ni][2 * half + 1] + bv1) * scale);
                if (mat == 2) {
                    // V natural layout, coalesced float2
                    float2 v; v.x = v0; v.y = v1;
                    *(float2*)(outp + ((size_t)(b * HH + h) * SS + s) * DHD + dh) = v;
                } else {
                    float* ob = outp + ((size_t)(b * HH + h) * SS + s) * DHD + dhg;
                    ob[p0] = v0;
                    ob[p1] = v1;
                }
            }
        }
    }
}

// ============================================================================
// Kernel 2: flash attention (tf32 mma, base-2 online softmax)
// grid = (16 q-tiles of 128, 64 bh), 128 threads (4 warps x 32 q-rows).
// 32-key stages, stride-72 smem (conflict-free for K, Q and V frags).
// P relayout via intra-quad shuffles (no P smem); QA reloaded from smem.
// 3 CTAs/SM target: smem 73728 B, regs capped at 168.
// ============================================================================
#define KST 72
#define KTILE_F (32 * KST)
#define Q_FLOATS (128 * KST)

__global__ __launch_bounds__(128, 3) void attn_kernel(float* __restrict__ out)
{
    extern __shared__ float sm[];
    float* QP = sm;                    // Q, persistent: 128 x 72
    float* Ks = sm + Q_FLOATS;         // 2 x 32 x 72
    float* Vs = Ks + 2 * KTILE_F;      // 2 x 32 x 72

    const int bh = blockIdx.y;
    const int q0 = blockIdx.x * 128;

    const float* qb = g_q + (size_t)bh * SS * DHD + (size_t)q0 * DHD;
    const float* kb = g_k + (size_t)bh * SS * DHD;
    const float* vb = g_v + (size_t)bh * SS * DHD;

    const int tid  = threadIdx.x;
    const int warp = tid >> 5;
    const int lane = tid & 31;
    const int g    = lane >> 2;
    const int tig  = lane & 3;

    // Load Q tile 128x64 (persistent)
    #pragma unroll
    for (int i = 0; i < 16; i++) {
        int idx = tid + i * 128;
        int r = idx >> 4, c = (idx & 15) << 2;
        *(float4*)&QP[r * KST + c] = *(const float4*)(qb + (size_t)r * DHD + c);
    }

    float O[2][8][4];
    #pragma unroll
    for (int mi = 0; mi < 2; mi++)
        #pragma unroll
        for (int ni = 0; ni < 8; ni++)
            #pragma unroll
            for (int r = 0; r < 4; r++) O[mi][ni][r] = 0.0f;

    float mrun[2][2], lrun[2][2];
    #pragma unroll
    for (int mi = 0; mi < 2; mi++) {
        mrun[mi][0] = -1e30f; mrun[mi][1] = -1e30f;
        lrun[mi][0] = 0.0f;   lrun[mi][1] = 0.0f;
    }

    auto load_kv = [&](int t, int st) {
        #pragma unroll
        for (int i = 0; i < 4; i++) {
            int idx = tid + i * 128;
            int r = idx >> 4, c = (idx & 15) << 2;
            cp16(&Ks[st * KTILE_F + r * KST + c], kb + (size_t)(t * 32 + r) * DHD + c);
        }
        #pragma unroll
        for (int i = 0; i < 4; i++) {
            int idx = tid + i * 128;
            int r = idx >> 4, c = (idx & 15) << 2;
            cp16(&Vs[st * KTILE_F + r * KST + c], vb + (size_t)(t * 32 + r) * DHD + c);
        }
        CP_COMMIT();
    };

    load_kv(0, 0);
    __syncthreads();   // Q visible to all warps

    const int qrow0 = warp * 32;
    const int s0l = (lane & ~3) | (tig >> 1);   // shuffle src for j=tig
    const int s2l = s0l + 2;                    // shuffle src for j=tig+4
    const bool bsel = (tig & 1);

    const int NT = SS / 32;   // 64 tiles
    for (int t = 0; t < NT; t++) {
        if (t + 1 < NT) { load_kv(t + 1, (t + 1) & 1); CP_WAIT(1); }
        else            { CP_WAIT(0); }
        __syncthreads();

        const float* Kst = Ks + (t & 1) * KTILE_F;
        const float* Vst = Vs + (t & 1) * KTILE_F;

        // S = Q @ K^T : 32 rows x 32 keys per warp (QA reloaded from smem)
        float S[2][4][4];
        #pragma unroll
        for (int mi = 0; mi < 2; mi++)
            #pragma unroll
            for (int ni = 0; ni < 4; ni++)
                #pragma unroll
                for (int r = 0; r < 4; r++) S[mi][ni][r] = 0.0f;

        #pragma unroll
        for (int kk = 0; kk < 8; kk++) {
            const int k8 = kk * 8;
            uint32_t QA[2][4];
            #pragma unroll
            for (int mi = 0; mi < 2; mi++) {
                const int qrow = qrow0 + mi * 16;
                float2 lo = *(const float2*)&QP[(qrow + g) * KST + k8 + 2 * tig];
                float2 hi = *(const float2*)&QP[(qrow + g + 8) * KST + k8 + 2 * tig];
                QA[mi][0] = __float_as_uint(lo.x);
                QA[mi][1] = __float_as_uint(hi.x);
                QA[mi][2] = __float_as_uint(lo.y);
                QA[mi][3] = __float_as_uint(hi.y);
            }
            #pragma unroll
            for (int ni = 0; ni < 4; ni++) {
                float2 bb = *(const float2*)&Kst[(ni * 8 + g) * KST + k8 + 2 * tig];
                uint32_t b0 = __float_as_uint(bb.x);
                uint32_t b1 = __float_as_uint(bb.y);
                #pragma unroll
                for (int mi = 0; mi < 2; mi++)
                    mma8(S[mi][ni][0], S[mi][ni][1], S[mi][ni][2], S[mi][ni][3],
                         QA[mi][0], QA[mi][1], QA[mi][2], QA[mi][3], b0, b1);
            }
        }

        // Base-2 online softmax per mi (row pairs g, g+8)
        #pragma unroll
        for (int mi = 0; mi < 2; mi++) {
            float mt0 = -1e30f, mt1 = -1e30f;
            #pragma unroll
            for (int ni = 0; ni < 4; ni++) {
                mt0 = fmaxf(mt0, fmaxf(S[mi][ni][0], S[mi][ni][1]));
                mt1 = fmaxf(mt1, fmaxf(S[mi][ni][2], S[mi][ni][3]));
            }
            mt0 = fmaxf(mt0, __shfl_xor_sync(0xffffffffu, mt0, 1));
            mt0 = fmaxf(mt0, __shfl_xor_sync(0xffffffffu, mt0, 2));
            mt1 = fmaxf(mt1, __shfl_xor_sync(0xffffffffu, mt1, 1));
            mt1 = fmaxf(mt1, __shfl_xor_sync(0xffffffffu, mt1, 2));

            const float mn0 = fmaxf(mrun[mi][0], mt0);
            const float mn1 = fmaxf(mrun[mi][1], mt1);
            const float al0 = exp2f(mrun[mi][0] - mn0);
            const float al1 = exp2f(mrun[mi][1] - mn1);

            float rs0 = 0.0f, rs1 = 0.0f;
            #pragma unroll
            for (int ni = 0; ni < 4; ni++) {
                S[mi][ni][0] = exp2f(S[mi][ni][0] - mn0);
                S[mi][ni][1] = exp2f(S[mi][ni][1] - mn0);
                S[mi][ni][2] = exp2f(S[mi][ni][2] - mn1);
                S[mi][ni][3] = exp2f(S[mi][ni][3] - mn1);
                rs0 += S[mi][ni][0] + S[mi][ni][1];
                rs1 += S[mi][ni][2] + S[mi][ni][3];
            }
            rs0 += __shfl_xor_sync(0xffffffffu, rs0, 1);
            rs0 += __shfl_xor_sync(0xffffffffu, rs0, 2);
            rs1 += __shfl_xor_sync(0xffffffffu, rs1, 1);
            rs1 += __shfl_xor_sync(0xffffffffu, rs1, 2);

            lrun[mi][0] = lrun[mi][0] * al0 + rs0;
            lrun[mi][1] = lrun[mi][1] * al1 + rs1;
            mrun[mi][0] = mn0;
            mrun[mi][1] = mn1;

            if (!__all_sync(0xffffffffu, (al0 == 1.0f) & (al1 == 1.0f))) {
                #pragma unroll
                for (int ni = 0; ni < 8; ni++) {
                    O[mi][ni][0] *= al0; O[mi][ni][1] *= al0;
                    O[mi][ni][2] *= al1; O[mi][ni][3] *= al1;
                }
            }

            // tf32-round P for the PV mma
            #pragma unroll
            for (int ni = 0; ni < 4; ni++) {
                S[mi][ni][0] = f2tff(S[mi][ni][0]);
                S[mi][ni][1] = f2tff(S[mi][ni][1]);
                S[mi][ni][2] = f2tff(S[mi][ni][2]);
                S[mi][ni][3] = f2tff(S[mi][ni][3]);
            }
        }

        // O += P @ V. A-frags for P via intra-quad shuffles:
        // C-frag thread (g,tig') holds P[g][8*ni+2*tig'(+1)], P[g+8][..].
        // A-frag thread (g,tig) needs P[g][8*kk+tig], P[g][8*kk+tig+4] (+rows g+8)
        //   -> src lane 4g+(tig>>1) (and +2), select low/high on tig&1.
        #pragma unroll
        for (int kk = 0; kk < 4; kk++) {
            const int k8 = kk * 8;
            uint32_t pa[2][4];
            #pragma unroll
            for (int mi = 0; mi < 2; mi++) {
                float v00 = __shfl_sync(0xffffffffu, S[mi][kk][0], s0l);
                float v01 = __shfl_sync(0xffffffffu, S[mi][kk][1], s0l);
                float v10 = __shfl_sync(0xffffffffu, S[mi][kk][2], s0l);
                float v11 = __shfl_sync(0xffffffffu, S[mi][kk][3], s0l);
                float w00 = __shfl_sync(0xffffffffu, S[mi][kk][0], s2l);
                float w01 = __shfl_sync(0xffffffffu, S[mi][kk][1], s2l);
                float w10 = __shfl_sync(0xffffffffu, S[mi][kk][2], s2l);
                float w11 = __shfl_sync(0xffffffffu, S[mi][kk][3], s2l);
                pa[mi][0] = __float_as_uint(bsel ? v01 : v00);  // P[g][k8+tig]
                pa[mi][1] = __float_as_uint(bsel ? v11 : v10);  // P[g+8][k8+tig]
                pa[mi][2] = __float_as_uint(bsel ? w01 : w00);  // P[g][k8+tig+4]
                pa[mi][3] = __float_as_uint(bsel ? w11 : w10);  // P[g+8][k8+tig+4]
            }
            #pragma unroll
            for (int ni = 0; ni < 8; ni++) {
                uint32_t b0 = __float_as_uint(Vst[(k8 + tig) * KST + ni * 8 + g]);
                uint32_t b1 = __float_as_uint(Vst[(k8 + tig + 4) * KST + ni * 8 + g]);
                #pragma unroll
                for (int mi = 0; mi < 2; mi++)
                    mma8(O[mi][ni][0], O[mi][ni][1], O[mi][ni][2], O[mi][ni][3],
                         pa[mi][0], pa[mi][1], pa[mi][2], pa[mi][3], b0, b1);
            }
        }
        __syncthreads();   // all warps done reading this stage before reload
    }

    // Normalize + write [B,S,H*DH]
    const int b = bh >> 4;
    const int h = bh & 15;
    #pragma unroll
    for (int mi = 0; mi < 2; mi++) {
        const float il0 = 1.0f / lrun[mi][0];
        const float il1 = 1.0f / lrun[mi][1];
        #pragma unroll
        for (int ni = 0; ni < 8; ni++) {
            const int dh = ni * 8 + 2 * tig;
            {
                int s = q0 + warp * 32 + mi * 16 + g;
                float2 v; v.x = O[mi][ni][0] * il0; v.y = O[mi][ni][1] * il0;
                *(float2*)(out + ((size_t)(b * SS + s) * HH + h) * DHD + dh) = v;
            }
            {
                int s = q0 + warp * 32 + mi * 16 + g + 8;
                float2 v; v.x = O[mi][ni][2] * il1; v.y = O[mi][ni][3] * il1;
                *(float2*)(out + ((size_t)(b * SS + s) * HH + h) * DHD + dh) = v;
            }
        }
    }
}

// ============================================================================
// Launch
// ============================================================================
extern "C" void kernel_launch(void* const* d_in, const int* in_sizes, int n_in,
                              void* d_out, int out_size)
{
    const float* x  = (const float*)d_in[0];
    const float* Wq = (const float*)d_in[1];
    const float* bq = (const float*)d_in[2];
    const float* Wk = (const float*)d_in[3];
    const float* bk = (const float*)d_in[4];
    const float* Wv = (const float*)d_in[5];
    const float* bv = (const float*)d_in[6];
    float* out = (float*)d_out;

    // Prep: permute+round x; transpose+permute+round W
    {
        int ngx = MTOT * DD / 8;
        cvt_x_kernel<<<ngx / 256, 256>>>((const float4*)x);
        dim3 gw(32, 32, 3);
        cvt_w_kernel<<<gw, dim3(32, 8)>>>(Wq, Wk, Wv);
    }

    // QKV GEMM
    {
        const int smem = (2 * XS_ST + 2 * WS_ST) * (int)sizeof(float);   // 81920
        cudaFuncSetAttribute(qkv_gemm_kernel,
                             cudaFuncAttributeMaxDynamicSharedMemorySize, smem);
        dim3 grd(MTOT / 128, 24);
        qkv_gemm_kernel<<<grd, 128, smem>>>(bq, bk, bv);
    }

    // Attention
    {
        const int smem = (Q_FLOATS + 4 * KTILE_F) * (int)sizeof(float);  // 73728
        cudaFuncSetAttribute(attn_kernel,
                             cudaFuncAttributeMaxDynamicSharedMemorySize, smem);
        dim3 grd(SS / 128, BB * HH);
        attn_kernel<<<grd, 128, smem>>>(out);
    }
}

// round 11
// speedup vs baseline: 1.1726x; 1.0737x over previous
#include <cuda_runtime.h>
#include <cstdint>

#define BB 4
#define SS 2048
#define HH 16
#define DHD 64
#define DD 1024
#define MTOT (BB * SS)   // 8192

// pos(k) within a group of 8: (k%4)*2 + k/4  -> pairs (t, t+4) become adjacent
// Scratch.
// g_q, g_k: [B,H,S,DH], DH pair-permuted, tf32-rounded. Q scaled by log2e/8.
// g_v: [B,H,S,DH] natural layout, tf32-rounded.
__device__ float g_q[(size_t)BB * HH * SS * DHD];
__device__ float g_k[(size_t)BB * HH * SS * DHD];
__device__ float g_v[(size_t)BB * HH * SS * DHD];
// g_xt: tf32-rounded x, K-dim pair-permuted. g_wtT: W^T [n][k], k pair-permuted.
__device__ float g_xt[(size_t)MTOT * DD];
__device__ float g_wtT[3][(size_t)DD * DD];

__device__ __forceinline__ uint32_t f2tf(float f) {
    uint32_t u;
    asm("cvt.rna.tf32.f32 %0, %1;" : "=r"(u) : "f"(f));
    return u;
}
__device__ __forceinline__ float f2tff(float f) { return __uint_as_float(f2tf(f)); }

__device__ __forceinline__ void mma8(float& d0, float& d1, float& d2, float& d3,
                                     uint32_t a0, uint32_t a1, uint32_t a2, uint32_t a3,
                                     uint32_t b0, uint32_t b1) {
    asm volatile(
        "mma.sync.aligned.m16n8k8.row.col.f32.tf32.tf32.f32 "
        "{%0,%1,%2,%3}, {%4,%5,%6,%7}, {%8,%9}, {%0,%1,%2,%3};"
        : "+f"(d0), "+f"(d1), "+f"(d2), "+f"(d3)
        : "r"(a0), "r"(a1), "r"(a2), "r"(a3), "r"(b0), "r"(b1));
}

__device__ __forceinline__ void cp16(void* smem, const void* gmem) {
    uint32_t s = (uint32_t)__cvta_generic_to_shared(smem);
    asm volatile("cp.async.cg.shared.global [%0], [%1], 16;" :: "r"(s), "l"(gmem));
}
#define CP_COMMIT() asm volatile("cp.async.commit_group;")
#define CP_WAIT(N)  asm volatile("cp.async.wait_group %0;" :: "n"(N))

// ============================================================================
// Kernel 0a: x -> tf32-rounded, K-dim pair-permuted.
// ============================================================================
__global__ __launch_bounds__(256) void cvt_x_kernel(const float4* __restrict__ src) {
    int j = blockIdx.x * 256 + threadIdx.x;
    float4 a = src[2 * j];
    float4 b = src[2 * j + 1];
    float4 o0, o1;
    o0.x = f2tff(a.x); o0.y = f2tff(b.x); o0.z = f2tff(a.y); o0.w = f2tff(b.y);
    o1.x = f2tff(a.z); o1.y = f2tff(b.z); o1.z = f2tff(a.w); o1.w = f2tff(b.w);
    ((float4*)g_xt)[2 * j]     = o0;
    ((float4*)g_xt)[2 * j + 1] = o1;
}

// ============================================================================
// Kernel 0b: W [k][n] -> Wt [n][k] tf32-rounded, k pair-permuted.
// ============================================================================
__global__ __launch_bounds__(256) void cvt_w_kernel(
    const float* __restrict__ Wq, const float* __restrict__ Wk,
    const float* __restrict__ Wv)
{
    __shared__ float tile[32][33];
    const int mat = blockIdx.z;
    const float* W = (mat == 0) ? Wq : (mat == 1) ? Wk : Wv;
    float* Wt = g_wtT[mat];
    const int k0 = blockIdx.x * 32;
    const int n0 = blockIdx.y * 32;
    const int tx = threadIdx.x, ty = threadIdx.y;

    #pragma unroll
    for (int i = 0; i < 4; i++)
        tile[ty + i * 8][tx] = W[(size_t)(k0 + ty + i * 8) * DD + n0 + tx];
    __syncthreads();
    const int kp = (tx & 24) + ((tx & 3) * 2 + ((tx >> 2) & 1));
    #pragma unroll
    for (int i = 0; i < 4; i++)
        Wt[(size_t)(n0 + ty + i * 8) * DD + k0 + kp] = f2tff(tile[tx][ty + i * 8]);
}

// ============================================================================
// Kernel 1: fused QKV projection GEMM (tf32 mma, cp.async 2-stage)
// 256 threads, 8 warps (2 m x 4 n), warp tile 64x32, 128x128 block tile.
// 2 CTAs/SM -> 16 warps/SM (4 per SMSP), acc 64 regs/thread.
// Epilogue: Q (scaled, DH-permuted), K (DH-permuted), V (natural, coalesced).
// ============================================================================
#define GST 40
#define XS_ST (128 * GST)
#define WS_ST (128 * GST)

__global__ __launch_bounds__(256, 2) void qkv_gemm_kernel(
    const float* __restrict__ bq, const float* __restrict__ bk,
    const float* __restrict__ bv)
{
    extern __shared__ float sm[];
    float* Xs = sm;
    float* Wsm = sm + 2 * XS_ST;

    const int mt = blockIdx.x;
    const int nt = blockIdx.y;
    const int mat = nt >> 3;
    const int n0 = (nt & 7) * 128;

    const float* Wtb = g_wtT[mat];
    const float* bias = (mat == 0) ? bq : (mat == 1) ? bk : bv;
    float* outp = (mat == 0) ? g_q : (mat == 1) ? g_k : g_v;
    const float scale = (mat == 0) ? 0.18033688f : 1.0f;   // log2e/8 for Q

    const int tid  = threadIdx.x;
    const int warp = tid >> 5;            // 0..7
    const int lane = tid & 31;
    const int g    = lane >> 2;
    const int tig  = lane & 3;
    const int wm   = (warp & 1) * 64;     // 2 m-warps
    const int wn   = (warp >> 1) * 32;    // 4 n-warps
    const int m0   = mt * 128;

    const float* xb = g_xt + (size_t)m0 * DD;

    float acc[4][4][4];
    #pragma unroll
    for (int mi = 0; mi < 4; mi++)
        #pragma unroll
        for (int ni = 0; ni < 4; ni++)
            #pragma unroll
            for (int r = 0; r < 4; r++) acc[mi][ni][r] = 0.0f;

    auto load_stage = [&](int t, int st) {
        const int k0 = t * 32;
        float* Xst = Xs + st * XS_ST;
        float* Wst = Wsm + st * WS_ST;
        #pragma unroll
        for (int i = 0; i < 4; i++) {
            int idx = tid + i * 256;
            int r = idx >> 3, c = (idx & 7) << 2;
            cp16(&Xst[r * GST + c], xb + (size_t)r * DD + k0 + c);
        }
        #pragma unroll
        for (int i = 0; i < 4; i++) {
            int idx = tid + i * 256;
            int r = idx >> 3, c = (idx & 7) << 2;
            cp16(&Wst[r * GST + c], Wtb + (size_t)(n0 + r) * DD + k0 + c);
        }
        CP_COMMIT();
    };

    load_stage(0, 0);

    const int NT = DD / 32;
    for (int t = 0; t < NT; t++) {
        if (t + 1 < NT) { load_stage(t + 1, (t + 1) & 1); CP_WAIT(1); }
        else            { CP_WAIT(0); }
        __syncthreads();

        const float* Xst = Xs + (t & 1) * XS_ST;
        const float* Wst = Wsm + (t & 1) * WS_ST;
        #pragma unroll
        for (int kk = 0; kk < 4; kk++) {
            const int k8 = kk * 8;
            uint32_t A[4][4];
            #pragma unroll
            for (int mi = 0; mi < 4; mi++) {
                const int row = wm + mi * 16;
                float2 lo = *(const float2*)&Xst[(row + g) * GST + k8 + 2 * tig];
                float2 hi = *(const float2*)&Xst[(row + g + 8) * GST + k8 + 2 * tig];
                A[mi][0] = __float_as_uint(lo.x);
                A[mi][1] = __float_as_uint(hi.x);
                A[mi][2] = __float_as_uint(lo.y);
                A[mi][3] = __float_as_uint(hi.y);
            }
            #pragma unroll
            for (int ni = 0; ni < 4; ni++) {
                const int col = wn + ni * 8 + g;
                float2 bb = *(const float2*)&Wst[col * GST + k8 + 2 * tig];
                uint32_t b0 = __float_as_uint(bb.x);
                uint32_t b1 = __float_as_uint(bb.y);
                #pragma unroll
                for (int mi = 0; mi < 4; mi++)
                    mma8(acc[mi][ni][0], acc[mi][ni][1], acc[mi][ni][2], acc[mi][ni][3],
                         A[mi][0], A[mi][1], A[mi][2], A[mi][3], b0, b1);
            }
        }
        __syncthreads();
    }

    // Epilogue
    #pragma unroll
    for (int mi = 0; mi < 4; mi++) {
        #pragma unroll
        for (int ni = 0; ni < 4; ni++) {
            const int n = n0 + wn + ni * 8 + 2 * tig;   // even
            const int h = n >> 6;
            const int dh = n & 63;
            const float bv0 = bias[n];
            const float bv1 = bias[n + 1];
            const int mbase = m0 + wm + mi * 16;
            const int dhg = dh & ~7;
            const int p0 = 2 * ((2 * tig) & 3) + (tig >> 1);
            const int p1 = 2 * ((2 * tig + 1) & 3) + ((2 * tig + 1) >> 2);
            #pragma unroll
            for (int half = 0; half < 2; half++) {
                const int m = mbase + g + half * 8;
                const int b = m >> 11, s = m & 2047;
                const float v0 = f2tff((acc[mi][ni][2 * half]     + bv0) * scale);
                const float v1 = f2tff((acc[mi][ni][2 * half + 1] + bv1) * scale);
                if (mat == 2) {
                    // V natural layout, coalesced float2
                    float2 v; v.x = v0; v.y = v1;
                    *(float2*)(outp + ((size_t)(b * HH + h) * SS + s) * DHD + dh) = v;
                } else {
                    float* ob = outp + ((size_t)(b * HH + h) * SS + s) * DHD + dhg;
                    ob[p0] = v0;
                    ob[p1] = v1;
                }
            }
        }
    }
}

// ============================================================================
// Kernel 2: flash attention (tf32 mma, base-2 online softmax) — UNCHANGED R8
// grid = (16 q-tiles of 128, 64 bh), 128 threads (4 warps x 32 q-rows).
// 32-key stages, stride-72 smem; shuffle P relayout; QA from smem; 3 CTAs/SM.
// ============================================================================
#define KST 72
#define KTILE_F (32 * KST)
#define Q_FLOATS (128 * KST)

__global__ __launch_bounds__(128, 3) void attn_kernel(float* __restrict__ out)
{
    extern __shared__ float sm[];
    float* QP = sm;                    // Q, persistent: 128 x 72
    float* Ks = sm + Q_FLOATS;         // 2 x 32 x 72
    float* Vs = Ks + 2 * KTILE_F;      // 2 x 32 x 72

    const int bh = blockIdx.y;
    const int q0 = blockIdx.x * 128;

    const float* qb = g_q + (size_t)bh * SS * DHD + (size_t)q0 * DHD;
    const float* kb = g_k + (size_t)bh * SS * DHD;
    const float* vb = g_v + (size_t)bh * SS * DHD;

    const int tid  = threadIdx.x;
    const int warp = tid >> 5;
    const int lane = tid & 31;
    const int g    = lane >> 2;
    const int tig  = lane & 3;

    // Load Q tile 128x64 (persistent)
    #pragma unroll
    for (int i = 0; i < 16; i++) {
        int idx = tid + i * 128;
        int r = idx >> 4, c = (idx & 15) << 2;
        *(float4*)&QP[r * KST + c] = *(const float4*)(qb + (size_t)r * DHD + c);
    }

    float O[2][8][4];
    #pragma unroll
    for (int mi = 0; mi < 2; mi++)
        #pragma unroll
        for (int ni = 0; ni < 8; ni++)
            #pragma unroll
            for (int r = 0; r < 4; r++) O[mi][ni][r] = 0.0f;

    float mrun[2][2], lrun[2][2];
    #pragma unroll
    for (int mi = 0; mi < 2; mi++) {
        mrun[mi][0] = -1e30f; mrun[mi][1] = -1e30f;
        lrun[mi][0] = 0.0f;   lrun[mi][1] = 0.0f;
    }

    auto load_kv = [&](int t, int st) {
        #pragma unroll
        for (int i = 0; i < 4; i++) {
            int idx = tid + i * 128;
            int r = idx >> 4, c = (idx & 15) << 2;
            cp16(&Ks[st * KTILE_F + r * KST + c], kb + (size_t)(t * 32 + r) * DHD + c);
        }
        #pragma unroll
        for (int i = 0; i < 4; i++) {
            int idx = tid + i * 128;
            int r = idx >> 4, c = (idx & 15) << 2;
            cp16(&Vs[st * KTILE_F + r * KST + c], vb + (size_t)(t * 32 + r) * DHD + c);
        }
        CP_COMMIT();
    };

    load_kv(0, 0);
    __syncthreads();   // Q visible to all warps

    const int qrow0 = warp * 32;
    const int s0l = (lane & ~3) | (tig >> 1);   // shuffle src for j=tig
    const int s2l = s0l + 2;                    // shuffle src for j=tig+4
    const bool bsel = (tig & 1);

    const int NT = SS / 32;   // 64 tiles
    for (int t = 0; t < NT; t++) {
        if (t + 1 < NT) { load_kv(t + 1, (t + 1) & 1); CP_WAIT(1); }
        else            { CP_WAIT(0); }
        __syncthreads();

        const float* Kst = Ks + (t & 1) * KTILE_F;
        const float* Vst = Vs + (t & 1) * KTILE_F;

        // S = Q @ K^T : 32 rows x 32 keys per warp (QA reloaded from smem)
        float S[2][4][4];
        #pragma unroll
        for (int mi = 0; mi < 2; mi++)
            #pragma unroll
            for (int ni = 0; ni < 4; ni++)
                #pragma unroll
                for (int r = 0; r < 4; r++) S[mi][ni][r] = 0.0f;

        #pragma unroll
        for (int kk = 0; kk < 8; kk++) {
            const int k8 = kk * 8;
            uint32_t QA[2][4];
            #pragma unroll
            for (int mi = 0; mi < 2; mi++) {
                const int qrow = qrow0 + mi * 16;
                float2 lo = *(const float2*)&QP[(qrow + g) * KST + k8 + 2 * tig];
                float2 hi = *(const float2*)&QP[(qrow + g + 8) * KST + k8 + 2 * tig];
                QA[mi][0] = __float_as_uint(lo.x);
                QA[mi][1] = __float_as_uint(hi.x);
                QA[mi][2] = __float_as_uint(lo.y);
                QA[mi][3] = __float_as_uint(hi.y);
            }
            #pragma unroll
            for (int ni = 0; ni < 4; ni++) {
                float2 bb = *(const float2*)&Kst[(ni * 8 + g) * KST + k8 + 2 * tig];
                uint32_t b0 = __float_as_uint(bb.x);
                uint32_t b1 = __float_as_uint(bb.y);
                #pragma unroll
                for (int mi = 0; mi < 2; mi++)
                    mma8(S[mi][ni][0], S[mi][ni][1], S[mi][ni][2], S[mi][ni][3],
                         QA[mi][0], QA[mi][1], QA[mi][2], QA[mi][3], b0, b1);
            }
        }

        // Base-2 online softmax per mi (row pairs g, g+8)
        #pragma unroll
        for (int mi = 0; mi < 2; mi++) {
            float mt0 = -1e30f, mt1 = -1e30f;
            #pragma unroll
            for (int ni = 0; ni < 4; ni++) {
                mt0 = fmaxf(mt0, fmaxf(S[mi][ni][0], S[mi][ni][1]));
                mt1 = fmaxf(mt1, fmaxf(S[mi][ni][2], S[mi][ni][3]));
            }
            mt0 = fmaxf(mt0, __shfl_xor_sync(0xffffffffu, mt0, 1));
            mt0 = fmaxf(mt0, __shfl_xor_sync(0xffffffffu, mt0, 2));
            mt1 = fmaxf(mt1, __shfl_xor_sync(0xffffffffu, mt1, 1));
            mt1 = fmaxf(mt1, __shfl_xor_sync(0xffffffffu, mt1, 2));

            const float mn0 = fmaxf(mrun[mi][0], mt0);
            const float mn1 = fmaxf(mrun[mi][1], mt1);
            const float al0 = exp2f(mrun[mi][0] - mn0);
            const float al1 = exp2f(mrun[mi][1] - mn1);

            float rs0 = 0.0f, rs1 = 0.0f;
            #pragma unroll
            for (int ni = 0; ni < 4; ni++) {
                S[mi][ni][0] = exp2f(S[mi][ni][0] - mn0);
                S[mi][ni][1] = exp2f(S[mi][ni][1] - mn0);
                S[mi][ni][2] = exp2f(S[mi][ni][2] - mn1);
                S[mi][ni][3] = exp2f(S[mi][ni][3] - mn1);
                rs0 += S[mi][ni][0] + S[mi][ni][1];
                rs1 += S[mi][ni][2] + S[mi][ni][3];
            }
            rs0 += __shfl_xor_sync(0xffffffffu, rs0, 1);
            rs0 += __shfl_xor_sync(0xffffffffu, rs0, 2);
            rs1 += __shfl_xor_sync(0xffffffffu, rs1, 1);
            rs1 += __shfl_xor_sync(0xffffffffu, rs1, 2);

            lrun[mi][0] = lrun[mi][0] * al0 + rs0;
            lrun[mi][1] = lrun[mi][1] * al1 + rs1;
            mrun[mi][0] = mn0;
            mrun[mi][1] = mn1;

            if (!__all_sync(0xffffffffu, (al0 == 1.0f) & (al1 == 1.0f))) {
                #pragma unroll
                for (int ni = 0; ni < 8; ni++) {
                    O[mi][ni][0] *= al0; O[mi][ni][1] *= al0;
                    O[mi][ni][2] *= al1; O[mi][ni][3] *= al1;
                }
            }

            // tf32-round P for the PV mma
            #pragma unroll
            for (int ni = 0; ni < 4; ni++) {
                S[mi][ni][0] = f2tff(S[mi][ni][0]);
                S[mi][ni][1] = f2tff(S[mi][ni][1]);
                S[mi][ni][2] = f2tff(S[mi][ni][2]);
                S[mi][ni][3] = f2tff(S[mi][ni][3]);
            }
        }

        // O += P @ V. A-frags for P via intra-quad shuffles.
        #pragma unroll
        for (int kk = 0; kk < 4; kk++) {
            const int k8 = kk * 8;
            uint32_t pa[2][4];
            #pragma unroll
            for (int mi = 0; mi < 2; mi++) {
                float v00 = __shfl_sync(0xffffffffu, S[mi][kk][0], s0l);
                float v01 = __shfl_sync(0xffffffffu, S[mi][kk][1], s0l);
                float v10 = __shfl_sync(0xffffffffu, S[mi][kk][2], s0l);
                float v11 = __shfl_sync(0xffffffffu, S[mi][kk][3], s0l);
                float w00 = __shfl_sync(0xffffffffu, S[mi][kk][0], s2l);
                float w01 = __shfl_sync(0xffffffffu, S[mi][kk][1], s2l);
                float w10 = __shfl_sync(0xffffffffu, S[mi][kk][2], s2l);
                float w11 = __shfl_sync(0xffffffffu, S[mi][kk][3], s2l);
                pa[mi][0] = __float_as_uint(bsel ? v01 : v00);  // P[g][k8+tig]
                pa[mi][1] = __float_as_uint(bsel ? v11 : v10);  // P[g+8][k8+tig]
                pa[mi][2] = __float_as_uint(bsel ? w01 : w00);  // P[g][k8+tig+4]
                pa[mi][3] = __float_as_uint(bsel ? w11 : w10);  // P[g+8][k8+tig+4]
            }
            #pragma unroll
            for (int ni = 0; ni < 8; ni++) {
                uint32_t b0 = __float_as_uint(Vst[(k8 + tig) * KST + ni * 8 + g]);
                uint32_t b1 = __float_as_uint(Vst[(k8 + tig + 4) * KST + ni * 8 + g]);
                #pragma unroll
                for (int mi = 0; mi < 2; mi++)
                    mma8(O[mi][ni][0], O[mi][ni][1], O[mi][ni][2], O[mi][ni][3],
                         pa[mi][0], pa[mi][1], pa[mi][2], pa[mi][3], b0, b1);
            }
        }
        __syncthreads();   // all warps done reading this stage before reload
    }

    // Normalize + write [B,S,H*DH]
    const int b = bh >> 4;
    const int h = bh & 15;
    #pragma unroll
    for (int mi = 0; mi < 2; mi++) {
        const float il0 = 1.0f / lrun[mi][0];
        const float il1 = 1.0f / lrun[mi][1];
        #pragma unroll
        for (int ni = 0; ni < 8; ni++) {
            const int dh = ni * 8 + 2 * tig;
            {
                int s = q0 + warp * 32 + mi * 16 + g;
                float2 v; v.x = O[mi][ni][0] * il0; v.y = O[mi][ni][1] * il0;
                *(float2*)(out + ((size_t)(b * SS + s) * HH + h) * DHD + dh) = v;
            }
            {
                int s = q0 + warp * 32 + mi * 16 + g + 8;
                float2 v; v.x = O[mi][ni][2] * il1; v.y = O[mi][ni][3] * il1;
                *(float2*)(out + ((size_t)(b * SS + s) * HH + h) * DHD + dh) = v;
            }
        }
    }
}

// ============================================================================
// Launch
// ============================================================================
extern "C" void kernel_launch(void* const* d_in, const int* in_sizes, int n_in,
                              void* d_out, int out_size)
{
    const float* x  = (const float*)d_in[0];
    const float* Wq = (const float*)d_in[1];
    const float* bq = (const float*)d_in[2];
    const float* Wk = (const float*)d_in[3];
    const float* bk = (const float*)d_in[4];
    const float* Wv = (const float*)d_in[5];
    const float* bv = (const float*)d_in[6];
    float* out = (float*)d_out;

    // Prep: permute+round x; transpose+permute+round W
    {
        int ngx = MTOT * DD / 8;
        cvt_x_kernel<<<ngx / 256, 256>>>((const float4*)x);
        dim3 gw(32, 32, 3);
        cvt_w_kernel<<<gw, dim3(32, 8)>>>(Wq, Wk, Wv);
    }

    // QKV GEMM
    {
        const int smem = (2 * XS_ST + 2 * WS_ST) * (int)sizeof(float);   // 81920
        cudaFuncSetAttribute(qkv_gemm_kernel,
                             cudaFuncAttributeMaxDynamicSharedMemorySize, smem);
        dim3 grd(MTOT / 128, 24);
        qkv_gemm_kernel<<<grd, 256, smem>>>(bq, bk, bv);
    }

    // Attention
    {
        const int smem = (Q_FLOATS + 4 * KTILE_F) * (int)sizeof(float);  // 73728
        cudaFuncSetAttribute(attn_kernel,
                             cudaFuncAttributeMaxDynamicSharedMemorySize, smem);
        dim3 grd(SS / 128, BB * HH);
        attn_kernel<<<grd, 128, smem>>>(out);
    }
}

// round 12
// speedup vs baseline: 1.2233x; 1.0432x over previous
#include <cuda_runtime.h>
#include <cstdint>

#define BB 4
#define SS 2048
#define HH 16
#define DHD 64
#define DD 1024
#define MTOT (BB * SS)   // 8192

// pos(k) within a group of 8: (k%4)*2 + k/4  -> pairs (t, t+4) become adjacent
// Scratch.
// g_q, g_k: [B,H,S,DH], DH pair-permuted, tf32-rounded. Q scaled by log2e/8.
// g_v: [B,H,S,DH] natural layout, tf32-rounded.
__device__ float g_q[(size_t)BB * HH * SS * DHD];
__device__ float g_k[(size_t)BB * HH * SS * DHD];
__device__ float g_v[(size_t)BB * HH * SS * DHD];
// g_xt: tf32-rounded x, K-dim pair-permuted. g_wtT: W^T [n][k], k pair-permuted.
__device__ float g_xt[(size_t)MTOT * DD];
__device__ float g_wtT[3][(size_t)DD * DD];

__device__ __forceinline__ uint32_t f2tf(float f) {
    uint32_t u;
    asm("cvt.rna.tf32.f32 %0, %1;" : "=r"(u) : "f"(f));
    return u;
}
__device__ __forceinline__ float f2tff(float f) { return __uint_as_float(f2tf(f)); }

__device__ __forceinline__ void mma8(float& d0, float& d1, float& d2, float& d3,
                                     uint32_t a0, uint32_t a1, uint32_t a2, uint32_t a3,
                                     uint32_t b0, uint32_t b1) {
    asm volatile(
        "mma.sync.aligned.m16n8k8.row.col.f32.tf32.tf32.f32 "
        "{%0,%1,%2,%3}, {%4,%5,%6,%7}, {%8,%9}, {%0,%1,%2,%3};"
        : "+f"(d0), "+f"(d1), "+f"(d2), "+f"(d3)
        : "r"(a0), "r"(a1), "r"(a2), "r"(a3), "r"(b0), "r"(b1));
}

__device__ __forceinline__ void cp16(void* smem, const void* gmem) {
    uint32_t s = (uint32_t)__cvta_generic_to_shared(smem);
    asm volatile("cp.async.cg.shared.global [%0], [%1], 16;" :: "r"(s), "l"(gmem));
}
#define CP_COMMIT() asm volatile("cp.async.commit_group;")
#define CP_WAIT(N)  asm volatile("cp.async.wait_group %0;" :: "n"(N))

// ============================================================================
// Kernel 0a: x -> tf32-rounded, K-dim pair-permuted.
// ============================================================================
__global__ __launch_bounds__(256) void cvt_x_kernel(const float4* __restrict__ src) {
    int j = blockIdx.x * 256 + threadIdx.x;
    float4 a = src[2 * j];
    float4 b = src[2 * j + 1];
    float4 o0, o1;
    o0.x = f2tff(a.x); o0.y = f2tff(b.x); o0.z = f2tff(a.y); o0.w = f2tff(b.y);
    o1.x = f2tff(a.z); o1.y = f2tff(b.z); o1.z = f2tff(a.w); o1.w = f2tff(b.w);
    ((float4*)g_xt)[2 * j]     = o0;
    ((float4*)g_xt)[2 * j + 1] = o1;
}

// ============================================================================
// Kernel 0b: W [k][n] -> Wt [n][k] tf32-rounded, k pair-permuted.
// ============================================================================
__global__ __launch_bounds__(256) void cvt_w_kernel(
    const float* __restrict__ Wq, const float* __restrict__ Wk,
    const float* __restrict__ Wv)
{
    __shared__ float tile[32][33];
    const int mat = blockIdx.z;
    const float* W = (mat == 0) ? Wq : (mat == 1) ? Wk : Wv;
    float* Wt = g_wtT[mat];
    const int k0 = blockIdx.x * 32;
    const int n0 = blockIdx.y * 32;
    const int tx = threadIdx.x, ty = threadIdx.y;

    #pragma unroll
    for (int i = 0; i < 4; i++)
        tile[ty + i * 8][tx] = W[(size_t)(k0 + ty + i * 8) * DD + n0 + tx];
    __syncthreads();
    const int kp = (tx & 24) + ((tx & 3) * 2 + ((tx >> 2) & 1));
    #pragma unroll
    for (int i = 0; i < 4; i++)
        Wt[(size_t)(n0 + ty + i * 8) * DD + k0 + kp] = f2tff(tile[tx][ty + i * 8]);
}

// ============================================================================
// Kernel 1: fused QKV projection GEMM (tf32 mma, cp.async 2-stage) — R10
// 256 threads, 8 warps (2 m x 4 n), warp tile 64x32, 128x128 block tile.
// ============================================================================
#define GST 40
#define XS_ST (128 * GST)
#define WS_ST (128 * GST)

__global__ __launch_bounds__(256, 2) void qkv_gemm_kernel(
    const float* __restrict__ bq, const float* __restrict__ bk,
    const float* __restrict__ bv)
{
    extern __shared__ float sm[];
    float* Xs = sm;
    float* Wsm = sm + 2 * XS_ST;

    const int mt = blockIdx.x;
    const int nt = blockIdx.y;
    const int mat = nt >> 3;
    const int n0 = (nt & 7) * 128;

    const float* Wtb = g_wtT[mat];
    const float* bias = (mat == 0) ? bq : (mat == 1) ? bk : bv;
    float* outp = (mat == 0) ? g_q : (mat == 1) ? g_k : g_v;
    const float scale = (mat == 0) ? 0.18033688f : 1.0f;   // log2e/8 for Q

    const int tid  = threadIdx.x;
    const int warp = tid >> 5;            // 0..7
    const int lane = tid & 31;
    const int g    = lane >> 2;
    const int tig  = lane & 3;
    const int wm   = (warp & 1) * 64;     // 2 m-warps
    const int wn   = (warp >> 1) * 32;    // 4 n-warps
    const int m0   = mt * 128;

    const float* xb = g_xt + (size_t)m0 * DD;

    float acc[4][4][4];
    #pragma unroll
    for (int mi = 0; mi < 4; mi++)
        #pragma unroll
        for (int ni = 0; ni < 4; ni++)
            #pragma unroll
            for (int r = 0; r < 4; r++) acc[mi][ni][r] = 0.0f;

    auto load_stage = [&](int t, int st) {
        const int k0 = t * 32;
        float* Xst = Xs + st * XS_ST;
        float* Wst = Wsm + st * WS_ST;
        #pragma unroll
        for (int i = 0; i < 4; i++) {
            int idx = tid + i * 256;
            int r = idx >> 3, c = (idx & 7) << 2;
            cp16(&Xst[r * GST + c], xb + (size_t)r * DD + k0 + c);
        }
        #pragma unroll
        for (int i = 0; i < 4; i++) {
            int idx = tid + i * 256;
            int r = idx >> 3, c = (idx & 7) << 2;
            cp16(&Wst[r * GST + c], Wtb + (size_t)(n0 + r) * DD + k0 + c);
        }
        CP_COMMIT();
    };

    load_stage(0, 0);

    const int NT = DD / 32;
    for (int t = 0; t < NT; t++) {
        if (t + 1 < NT) { load_stage(t + 1, (t + 1) & 1); CP_WAIT(1); }
        else            { CP_WAIT(0); }
        __syncthreads();

        const float* Xst = Xs + (t & 1) * XS_ST;
        const float* Wst = Wsm + (t & 1) * WS_ST;
        #pragma unroll
        for (int kk = 0; kk < 4; kk++) {
            const int k8 = kk * 8;
            uint32_t A[4][4];
            #pragma unroll
            for (int mi = 0; mi < 4; mi++) {
                const int row = wm + mi * 16;
                float2 lo = *(const float2*)&Xst[(row + g) * GST + k8 + 2 * tig];
                float2 hi = *(const float2*)&Xst[(row + g + 8) * GST + k8 + 2 * tig];
                A[mi][0] = __float_as_uint(lo.x);
                A[mi][1] = __float_as_uint(hi.x);
                A[mi][2] = __float_as_uint(lo.y);
                A[mi][3] = __float_as_uint(hi.y);
            }
            #pragma unroll
            for (int ni = 0; ni < 4; ni++) {
                const int col = wn + ni * 8 + g;
                float2 bb = *(const float2*)&Wst[col * GST + k8 + 2 * tig];
                uint32_t b0 = __float_as_uint(bb.x);
                uint32_t b1 = __float_as_uint(bb.y);
                #pragma unroll
                for (int mi = 0; mi < 4; mi++)
                    mma8(acc[mi][ni][0], acc[mi][ni][1], acc[mi][ni][2], acc[mi][ni][3],
                         A[mi][0], A[mi][1], A[mi][2], A[mi][3], b0, b1);
            }
        }
        __syncthreads();
    }

    // Epilogue
    #pragma unroll
    for (int mi = 0; mi < 4; mi++) {
        #pragma unroll
        for (int ni = 0; ni < 4; ni++) {
            const int n = n0 + wn + ni * 8 + 2 * tig;   // even
            const int h = n >> 6;
            const int dh = n & 63;
            const float bv0 = bias[n];
            const float bv1 = bias[n + 1];
            const int mbase = m0 + wm + mi * 16;
            const int dhg = dh & ~7;
            const int p0 = 2 * ((2 * tig) & 3) + (tig >> 1);
            const int p1 = 2 * ((2 * tig + 1) & 3) + ((2 * tig + 1) >> 2);
            #pragma unroll
            for (int half = 0; half < 2; half++) {
                const int m = mbase + g + half * 8;
                const int b = m >> 11, s = m & 2047;
                const float v0 = f2tff((acc[mi][ni][2 * half]     + bv0) * scale);
                const float v1 = f2tff((acc[mi][ni][2 * half + 1] + bv1) * scale);
                if (mat == 2) {
                    // V natural layout, coalesced float2
                    float2 v; v.x = v0; v.y = v1;
                    *(float2*)(outp + ((size_t)(b * HH + h) * SS + s) * DHD + dh) = v;
                } else {
                    float* ob = outp + ((size_t)(b * HH + h) * SS + s) * DHD + dhg;
                    ob[p0] = v0;
                    ob[p1] = v1;
                }
            }
        }
    }
}

// ============================================================================
// Kernel 2: flash attention (tf32 mma, base-2 online softmax)
// grid = (16 q-tiles of 128, 64 bh), 128 threads (4 warps x 32 q-rows).
// 32-key stages, stride-72 smem; QA from smem; 3 CTAs/SM.
// NEW: K tile rows permuted within groups of 8 (key u -> row pos(u)) so the
// QK^T C-fragment IS the PV A-fragment (register renaming; no shuffles).
// V stays natural; softmax is permutation-invariant.
// ============================================================================
#define KST 72
#define KTILE_F (32 * KST)
#define Q_FLOATS (128 * KST)

__global__ __launch_bounds__(128, 3) void attn_kernel(float* __restrict__ out)
{
    extern __shared__ float sm[];
    float* QP = sm;                    // Q, persistent: 128 x 72
    float* Ks = sm + Q_FLOATS;         // 2 x 32 x 72
    float* Vs = Ks + 2 * KTILE_F;      // 2 x 32 x 72

    const int bh = blockIdx.y;
    const int q0 = blockIdx.x * 128;

    const float* qb = g_q + (size_t)bh * SS * DHD + (size_t)q0 * DHD;
    const float* kb = g_k + (size_t)bh * SS * DHD;
    const float* vb = g_v + (size_t)bh * SS * DHD;

    const int tid  = threadIdx.x;
    const int warp = tid >> 5;
    const int lane = tid & 31;
    const int g    = lane >> 2;
    const int tig  = lane & 3;

    // Load Q tile 128x64 (persistent)
    #pragma unroll
    for (int i = 0; i < 16; i++) {
        int idx = tid + i * 128;
        int r = idx >> 4, c = (idx & 15) << 2;
        *(float4*)&QP[r * KST + c] = *(const float4*)(qb + (size_t)r * DHD + c);
    }

    float O[2][8][4];
    #pragma unroll
    for (int mi = 0; mi < 2; mi++)
        #pragma unroll
        for (int ni = 0; ni < 8; ni++)
            #pragma unroll
            for (int r = 0; r < 4; r++) O[mi][ni][r] = 0.0f;

    float mrun[2][2], lrun[2][2];
    #pragma unroll
    for (int mi = 0; mi < 2; mi++) {
        mrun[mi][0] = -1e30f; mrun[mi][1] = -1e30f;
        lrun[mi][0] = 0.0f;   lrun[mi][1] = 0.0f;
    }

    auto load_kv = [&](int t, int st) {
        #pragma unroll
        for (int i = 0; i < 4; i++) {
            int idx = tid + i * 128;
            int r = idx >> 4, c = (idx & 15) << 2;
            // permuted dst row: key r -> row (r&~7) | pos(r&7), pos(u)=(u%4)*2+u/4
            int rp = (r & ~7) | (((r & 3) << 1) | ((r >> 2) & 1));
            cp16(&Ks[st * KTILE_F + rp * KST + c], kb + (size_t)(t * 32 + r) * DHD + c);
        }
        #pragma unroll
        for (int i = 0; i < 4; i++) {
            int idx = tid + i * 128;
            int r = idx >> 4, c = (idx & 15) << 2;
            cp16(&Vs[st * KTILE_F + r * KST + c], vb + (size_t)(t * 32 + r) * DHD + c);
        }
        CP_COMMIT();
    };

    load_kv(0, 0);
    __syncthreads();   // Q visible to all warps

    const int qrow0 = warp * 32;

    const int NT = SS / 32;   // 64 tiles
    for (int t = 0; t < NT; t++) {
        if (t + 1 < NT) { load_kv(t + 1, (t + 1) & 1); CP_WAIT(1); }
        else            { CP_WAIT(0); }
        __syncthreads();

        const float* Kst = Ks + (t & 1) * KTILE_F;
        const float* Vst = Vs + (t & 1) * KTILE_F;

        // S = Q @ K^T : 32 rows x 32 keys per warp (QA reloaded from smem).
        // mma col c within each 8-block = key sigma(c); thread (g,t) ends up
        // holding keys {t, t+4} per 8-block — the PV A-fragment layout.
        float S[2][4][4];
        #pragma unroll
        for (int mi = 0; mi < 2; mi++)
            #pragma unroll
            for (int ni = 0; ni < 4; ni++)
                #pragma unroll
                for (int r = 0; r < 4; r++) S[mi][ni][r] = 0.0f;

        #pragma unroll
        for (int kk = 0; kk < 8; kk++) {
            const int k8 = kk * 8;
            uint32_t QA[2][4];
            #pragma unroll
            for (int mi = 0; mi < 2; mi++) {
                const int qrow = qrow0 + mi * 16;
                float2 lo = *(const float2*)&QP[(qrow + g) * KST + k8 + 2 * tig];
                float2 hi = *(const float2*)&QP[(qrow + g + 8) * KST + k8 + 2 * tig];
                QA[mi][0] = __float_as_uint(lo.x);
                QA[mi][1] = __float_as_uint(hi.x);
                QA[mi][2] = __float_as_uint(lo.y);
                QA[mi][3] = __float_as_uint(hi.y);
            }
            #pragma unroll
            for (int ni = 0; ni < 4; ni++) {
                float2 bb = *(const float2*)&Kst[(ni * 8 + g) * KST + k8 + 2 * tig];
                uint32_t b0 = __float_as_uint(bb.x);
                uint32_t b1 = __float_as_uint(bb.y);
                #pragma unroll
                for (int mi = 0; mi < 2; mi++)
                    mma8(S[mi][ni][0], S[mi][ni][1], S[mi][ni][2], S[mi][ni][3],
                         QA[mi][0], QA[mi][1], QA[mi][2], QA[mi][3], b0, b1);
            }
        }

        // Base-2 online softmax per mi (row pairs g, g+8); permutation-invariant
        #pragma unroll
        for (int mi = 0; mi < 2; mi++) {
            float mt0 = -1e30f, mt1 = -1e30f;
            #pragma unroll
            for (int ni = 0; ni < 4; ni++) {
                mt0 = fmaxf(mt0, fmaxf(S[mi][ni][0], S[mi][ni][1]));
                mt1 = fmaxf(mt1, fmaxf(S[mi][ni][2], S[mi][ni][3]));
            }
            mt0 = fmaxf(mt0, __shfl_xor_sync(0xffffffffu, mt0, 1));
            mt0 = fmaxf(mt0, __shfl_xor_sync(0xffffffffu, mt0, 2));
            mt1 = fmaxf(mt1, __shfl_xor_sync(0xffffffffu, mt1, 1));
            mt1 = fmaxf(mt1, __shfl_xor_sync(0xffffffffu, mt1, 2));

            const float mn0 = fmaxf(mrun[mi][0], mt0);
            const float mn1 = fmaxf(mrun[mi][1], mt1);
            const float al0 = exp2f(mrun[mi][0] - mn0);
            const float al1 = exp2f(mrun[mi][1] - mn1);

            float rs0 = 0.0f, rs1 = 0.0f;
            #pragma unroll
            for (int ni = 0; ni < 4; ni++) {
                S[mi][ni][0] = exp2f(S[mi][ni][0] - mn0);
                S[mi][ni][1] = exp2f(S[mi][ni][1] - mn0);
                S[mi][ni][2] = exp2f(S[mi][ni][2] - mn1);
                S[mi][ni][3] = exp2f(S[mi][ni][3] - mn1);
                rs0 += S[mi][ni][0] + S[mi][ni][1];
                rs1 += S[mi][ni][2] + S[mi][ni][3];
            }
            rs0 += __shfl_xor_sync(0xffffffffu, rs0, 1);
            rs0 += __shfl_xor_sync(0xffffffffu, rs0, 2);
            rs1 += __shfl_xor_sync(0xffffffffu, rs1, 1);
            rs1 += __shfl_xor_sync(0xffffffffu, rs1, 2);

            lrun[mi][0] = lrun[mi][0] * al0 + rs0;
            lrun[mi][1] = lrun[mi][1] * al1 + rs1;
            mrun[mi][0] = mn0;
            mrun[mi][1] = mn1;

            if (!__all_sync(0xffffffffu, (al0 == 1.0f) & (al1 == 1.0f))) {
                #pragma unroll
                for (int ni = 0; ni < 8; ni++) {
                    O[mi][ni][0] *= al0; O[mi][ni][1] *= al0;
                    O[mi][ni][2] *= al1; O[mi][ni][3] *= al1;
                }
            }

            // tf32-round P for the PV mma
            #pragma unroll
            for (int ni = 0; ni < 4; ni++) {
                S[mi][ni][0] = f2tff(S[mi][ni][0]);
                S[mi][ni][1] = f2tff(S[mi][ni][1]);
                S[mi][ni][2] = f2tff(S[mi][ni][2]);
                S[mi][ni][3] = f2tff(S[mi][ni][3]);
            }
        }

        // O += P @ V. Thanks to the K-row permutation, the C-frag S[mi][kk]
        // IS the A-frag for contraction block kk:
        //   a0 = P[g][key k8+t]     = c0 (S[..][0])
        //   a1 = P[g+8][key k8+t]   = c2 (S[..][2])
        //   a2 = P[g][key k8+t+4]   = c1 (S[..][1])
        //   a3 = P[g+8][key k8+t+4] = c3 (S[..][3])
        #pragma unroll
        for (int kk = 0; kk < 4; kk++) {
            const int k8 = kk * 8;
            uint32_t pa[2][4];
            #pragma unroll
            for (int mi = 0; mi < 2; mi++) {
                pa[mi][0] = __float_as_uint(S[mi][kk][0]);
                pa[mi][1] = __float_as_uint(S[mi][kk][2]);
                pa[mi][2] = __float_as_uint(S[mi][kk][1]);
                pa[mi][3] = __float_as_uint(S[mi][kk][3]);
            }
            #pragma unroll
            for (int ni = 0; ni < 8; ni++) {
                uint32_t b0 = __float_as_uint(Vst[(k8 + tig) * KST + ni * 8 + g]);
                uint32_t b1 = __float_as_uint(Vst[(k8 + tig + 4) * KST + ni * 8 + g]);
                #pragma unroll
                for (int mi = 0; mi < 2; mi++)
                    mma8(O[mi][ni][0], O[mi][ni][1], O[mi][ni][2], O[mi][ni][3],
                         pa[mi][0], pa[mi][1], pa[mi][2], pa[mi][3], b0, b1);
            }
        }
        __syncthreads();   // all warps done reading this stage before reload
    }

    // Normalize + write [B,S,H*DH]
    const int b = bh >> 4;
    const int h = bh & 15;
    #pragma unroll
    for (int mi = 0; mi < 2; mi++) {
        const float il0 = 1.0f / lrun[mi][0];
        const float il1 = 1.0f / lrun[mi][1];
        #pragma unroll
        for (int ni = 0; ni < 8; ni++) {
            const int dh = ni * 8 + 2 * tig;
            {
                int s = q0 + warp * 32 + mi * 16 + g;
                float2 v; v.x = O[mi][ni][0] * il0; v.y = O[mi][ni][1] * il0;
                *(float2*)(out + ((size_t)(b * SS + s) * HH + h) * DHD + dh) = v;
            }
            {
                int s = q0 + warp * 32 + mi * 16 + g + 8;
                float2 v; v.x = O[mi][ni][2] * il1; v.y = O[mi][ni][3] * il1;
                *(float2*)(out + ((size_t)(b * SS + s) * HH + h) * DHD + dh) = v;
            }
        }
    }
}

// ============================================================================
// Launch
// ============================================================================
extern "C" void kernel_launch(void* const* d_in, const int* in_sizes, int n_in,
                              void* d_out, int out_size)
{
    const float* x  = (const float*)d_in[0];
    const float* Wq = (const float*)d_in[1];
    const float* bq = (const float*)d_in[2];
    const float* Wk = (const float*)d_in[3];
    const float* bk = (const float*)d_in[4];
    const float* Wv = (const float*)d_in[5];
    const float* bv = (const float*)d_in[6];
    float* out = (float*)d_out;

    // Prep: permute+round x; transpose+permute+round W
    {
        int ngx = MTOT * DD / 8;
        cvt_x_kernel<<<ngx / 256, 256>>>((const float4*)x);
        dim3 gw(32, 32, 3);
        cvt_w_kernel<<<gw, dim3(32, 8)>>>(Wq, Wk, Wv);
    }

    // QKV GEMM
    {
        const int smem = (2 * XS_ST + 2 * WS_ST) * (int)sizeof(float);   // 81920
        cudaFuncSetAttribute(qkv_gemm_kernel,
                             cudaFuncAttributeMaxDynamicSharedMemorySize, smem);
        dim3 grd(MTOT / 128, 24);
        qkv_gemm_kernel<<<grd, 256, smem>>>(bq, bk, bv);
    }

    // Attention
    {
        const int smem = (Q_FLOATS + 4 * KTILE_F) * (int)sizeof(float);  // 73728
        cudaFuncSetAttribute(attn_kernel,
                             cudaFuncAttributeMaxDynamicSharedMemorySize, smem);
        dim3 grd(SS / 128, BB * HH);
        attn_kernel<<<grd, 128, smem>>>(out);
    }
}